// round 1
// baseline (speedup 1.0000x reference)
#include <cuda_runtime.h>
#include <math.h>

#define T_SEQ   512
#define IN_DIM  1024
#define H_DIM   2048
#define OUT_DIM 1024
#define GRID_P  148
#define NTHR    256
#define MAXR    14                      // ceil(2048/148)
#define SMEM_BYTES (2 * MAXR * H_DIM * 4)   // 229376 B: W_h2h1 + W_h2h2 row caches

// ---------------- device scratch (static globals: no allocation allowed) ----
__device__ float g_pre1[(size_t)T_SEQ * H_DIM];   // x@W_i2h1^T + b_i2h1 + b_h2h1
__device__ float g_h1[2][H_DIM];
__device__ float g_h2[2][H_DIM];
__device__ unsigned g_bar_count;                  // zero-initialized; self-resetting
__device__ volatile unsigned g_bar_gen;

__device__ __forceinline__ float dot4(float4 a, float4 b) {
    return a.x * b.x + a.y * b.y + a.z * b.z + a.w * b.w;
}

// Sense-reversing grid barrier (all GRID_P CTAs guaranteed co-resident:
// 224KB dynamic smem -> 1 CTA/SM, GRID_P=148 <= SM count on B300/GB300).
__device__ __forceinline__ void grid_bar() {
    __syncthreads();
    if (threadIdx.x == 0) {
        __threadfence();                       // release our CTA's stores to L2
        unsigned gen = g_bar_gen;
        if (atomicAdd(&g_bar_count, 1u) == GRID_P - 1u) {
            g_bar_count = 0;
            __threadfence();
            g_bar_gen = gen + 1u;
        } else {
            while (g_bar_gen == gen) { }
        }
        __threadfence();                       // acquire
    }
    __syncthreads();
}

// ---------------------------------------------------------------------------
// Kernel 1: pre1[t][j] = sum_k x[t][k]*W_i2h1[j][k] + b_i2h1[j] + b_h2h1[j]
// Tiled GEMM: BT=64 (t) x BJ=128 (j), BK=32, 128 threads, 8x8 microtile.
// ---------------------------------------------------------------------------
#define BT 64
#define BJ 128
#define BK 32

__global__ __launch_bounds__(128) void pre_gemm(
    const float* __restrict__ X,        // [512,1024]
    const float* __restrict__ W,        // [2048,1024]
    const float* __restrict__ b1,
    const float* __restrict__ b2)
{
    __shared__ float Xs[BT][BK + 1];
    __shared__ float Ws[BJ][BK + 1];
    const int tid = threadIdx.x;
    const int bt = blockIdx.y * BT;
    const int bj = blockIdx.x * BJ;
    const int tx = tid & 15;   // j group (8 rows each)
    const int ty = tid >> 4;   // t group (8 rows each)

    float acc[8][8];
#pragma unroll
    for (int i = 0; i < 8; i++)
#pragma unroll
        for (int j = 0; j < 8; j++) acc[i][j] = 0.f;

    for (int k0 = 0; k0 < IN_DIM; k0 += BK) {
        // load X tile (64x32 floats) via float4
#pragma unroll
        for (int i = tid; i < BT * (BK / 4); i += 128) {
            int t = i / (BK / 4), kq = i % (BK / 4);
            float4 v = *(const float4*)(X + (size_t)(bt + t) * IN_DIM + k0 + kq * 4);
            Xs[t][kq * 4 + 0] = v.x; Xs[t][kq * 4 + 1] = v.y;
            Xs[t][kq * 4 + 2] = v.z; Xs[t][kq * 4 + 3] = v.w;
        }
        // load W tile (128x32 floats)
#pragma unroll
        for (int i = tid; i < BJ * (BK / 4); i += 128) {
            int j = i / (BK / 4), kq = i % (BK / 4);
            float4 v = *(const float4*)(W + (size_t)(bj + j) * IN_DIM + k0 + kq * 4);
            Ws[j][kq * 4 + 0] = v.x; Ws[j][kq * 4 + 1] = v.y;
            Ws[j][kq * 4 + 2] = v.z; Ws[j][kq * 4 + 3] = v.w;
        }
        __syncthreads();
#pragma unroll 8
        for (int kk = 0; kk < BK; kk++) {
            float a[8], b[8];
#pragma unroll
            for (int i = 0; i < 8; i++) a[i] = Xs[ty * 8 + i][kk];
#pragma unroll
            for (int j = 0; j < 8; j++) b[j] = Ws[tx * 8 + j][kk];
#pragma unroll
            for (int i = 0; i < 8; i++)
#pragma unroll
                for (int j = 0; j < 8; j++) acc[i][j] += a[i] * b[j];
        }
        __syncthreads();
    }
#pragma unroll
    for (int i = 0; i < 8; i++) {
        int t = bt + ty * 8 + i;
#pragma unroll
        for (int j = 0; j < 8; j++) {
            int col = bj + tx * 8 + j;
            g_pre1[(size_t)t * H_DIM + col] = acc[i][j] + __ldg(b1 + col) + __ldg(b2 + col);
        }
    }
}

// ---------------------------------------------------------------------------
// Kernel 2: persistent sequential RNN loop.
// CTA b owns rows [b*H/G, (b+1)*H/G) of h1 and h2 for ALL steps.
// W_h2h1 rows + W_h2h2 rows cached in SMEM (224KB); W_i2h2 rows held in
// registers (weight-stationary: thread t owns columns 4t..4t+3 and
// 1024+4t..1024+4t+3 of every owned row).
// ---------------------------------------------------------------------------
__global__ __launch_bounds__(NTHR, 1) void rnn_persistent(
    const float* __restrict__ W_h2h1,
    const float* __restrict__ W_i2h2,
    const float* __restrict__ b_i2h2,
    const float* __restrict__ W_h2h2,
    const float* __restrict__ b_h2h2)
{
    extern __shared__ float smem[];
    float* Wsh1 = smem;                    // [MAXR][2048]
    float* Wsh2 = smem + MAXR * H_DIM;     // [MAXR][2048]
    __shared__ float red[MAXR][8];
    __shared__ float bsum[MAXR];

    const int tid = threadIdx.x;
    const int bid = blockIdx.x;
    const int r0 = (bid * H_DIM) / GRID_P;
    const int r1 = ((bid + 1) * H_DIM) / GRID_P;
    const int nr = r1 - r0;                // 13 or 14
    const int lane = tid & 31;
    const int wid = tid >> 5;

    // init h buffers (parity 0) + fused layer-2 bias
    if (tid < nr) {
        g_h1[0][r0 + tid] = 0.f;
        g_h2[0][r0 + tid] = 0.f;
        bsum[tid] = __ldg(b_i2h2 + r0 + tid) + __ldg(b_h2h2 + r0 + tid);
    }

    // SMEM weight caches (own rows of W_h2h1, W_h2h2)
    {
        const float4* s1 = (const float4*)(W_h2h1 + (size_t)r0 * H_DIM);
        const float4* s2 = (const float4*)(W_h2h2 + (size_t)r0 * H_DIM);
        float4* d1 = (float4*)Wsh1;
        float4* d2 = (float4*)Wsh2;
        const int n4 = nr * (H_DIM / 4);
        for (int i = tid; i < n4; i += NTHR) { d1[i] = s1[i]; d2[i] = s2[i]; }
    }

    // Register-stationary W_i2h2: 2 float4 per owned row per thread
    float4 wr0[MAXR], wr1[MAXR];
#pragma unroll
    for (int rr = 0; rr < MAXR; rr++) {
        int r = (rr < nr) ? (r0 + rr) : r0;      // clamp (dummy rows never stored)
        const float4* wp = (const float4*)(W_i2h2 + (size_t)r * H_DIM);
        wr0[rr] = wp[tid];
        wr1[rr] = wp[tid + 256];
    }

    grid_bar();   // all caches + h zeros visible everywhere

    // h chunks carried in registers
    float4 a0 = make_float4(0.f, 0.f, 0.f, 0.f), a1 = a0;   // h1(t-1): starts 0
    int p = 0;
    for (int t = 0; t < T_SEQ; t++) {
        // prefetch h2(t-1) chunk (ready since end barrier of step t-1)
        float4 c0 = __ldcg((const float4*)g_h2[p] + tid);
        float4 c1 = __ldcg((const float4*)g_h2[p] + tid + 256);

        // -------- phase A: h1(t) = tanh(pre1[t] + W_h2h1 @ h1(t-1)) --------
#pragma unroll
        for (int rr = 0; rr < MAXR; rr++) {
            const float* w = Wsh1 + rr * H_DIM;
            float4 w0 = *(const float4*)(w + 4 * tid);
            float4 w1 = *(const float4*)(w + 4 * tid + 1024);
            float acc = dot4(w0, a0) + dot4(w1, a1);
#pragma unroll
            for (int off = 16; off; off >>= 1)
                acc += __shfl_xor_sync(0xffffffffu, acc, off);
            if (lane == 0) red[rr][wid] = acc;
        }
        __syncthreads();
        if (tid < nr) {
            float s = g_pre1[(size_t)t * H_DIM + r0 + tid];
#pragma unroll
            for (int w = 0; w < 8; w++) s += red[tid][w];
            g_h1[1 - p][r0 + tid] = tanhf(s);
        }
        grid_bar();

        // -------- phase B: h2(t) = tanh(W_i2h2@h1(t) + W_h2h2@h2(t-1) + b) --
        float4 n0 = __ldcg((const float4*)g_h1[1 - p] + tid);
        float4 n1 = __ldcg((const float4*)g_h1[1 - p] + tid + 256);
#pragma unroll
        for (int rr = 0; rr < MAXR; rr++) {
            const float* w = Wsh2 + rr * H_DIM;
            float4 w0 = *(const float4*)(w + 4 * tid);
            float4 w1 = *(const float4*)(w + 4 * tid + 1024);
            float acc = dot4(wr0[rr], n0) + dot4(wr1[rr], n1)
                      + dot4(w0, c0) + dot4(w1, c1);
#pragma unroll
            for (int off = 16; off; off >>= 1)
                acc += __shfl_xor_sync(0xffffffffu, acc, off);
            if (lane == 0) red[rr][wid] = acc;
        }
        __syncthreads();
        if (tid < nr) {
            float s = bsum[tid];
#pragma unroll
            for (int w = 0; w < 8; w++) s += red[tid][w];
            g_h2[1 - p][r0 + tid] = tanhf(s);
        }
        grid_bar();

        a0 = n0; a1 = n1;   // h1(t) chunk becomes next step's h1(t-1)
        p ^= 1;
    }
    // final h2 is in g_h2[0] (t=511: p=1, wrote parity 0)
}

// ---------------------------------------------------------------------------
// Kernel 3: out[j] = h2_final @ W_h2o2[j]^T + b_h2o2[j]
// ---------------------------------------------------------------------------
__global__ __launch_bounds__(256) void out_gemv(
    const float* __restrict__ W,        // [1024,2048]
    const float* __restrict__ b,
    float* __restrict__ out)
{
    const int lane = threadIdx.x & 31;
    const int warp = threadIdx.x >> 5;
    const int row = blockIdx.x * 8 + warp;
    const float4* wp = (const float4*)(W + (size_t)row * H_DIM);
    const float4* hp = (const float4*)g_h2[0];
    float acc = 0.f;
#pragma unroll
    for (int i = 0; i < 16; i++) {
        float4 w4 = __ldg(wp + i * 32 + lane);
        float4 h4 = __ldcg(hp + i * 32 + lane);
        acc += dot4(w4, h4);
    }
#pragma unroll
    for (int off = 16; off; off >>= 1)
        acc += __shfl_xor_sync(0xffffffffu, acc, off);
    if (lane == 0) out[row] = acc + __ldg(b + row);
}

// ---------------------------------------------------------------------------
extern "C" void kernel_launch(void* const* d_in, const int* in_sizes, int n_in,
                              void* d_out, int out_size)
{
    const float* word   = (const float*)d_in[0];
    const float* W_i2h1 = (const float*)d_in[1];
    const float* b_i2h1 = (const float*)d_in[2];
    const float* W_h2h1 = (const float*)d_in[3];
    const float* b_h2h1 = (const float*)d_in[4];
    // d_in[5], d_in[6]: W_h2o1 / b_h2o1 — dead code in reference
    const float* W_i2h2 = (const float*)d_in[7];
    const float* b_i2h2 = (const float*)d_in[8];
    const float* W_h2h2 = (const float*)d_in[9];
    const float* b_h2h2 = (const float*)d_in[10];
    const float* W_h2o2 = (const float*)d_in[11];
    const float* b_h2o2 = (const float*)d_in[12];
    float* out = (float*)d_out;

    cudaFuncSetAttribute(rnn_persistent,
                         cudaFuncAttributeMaxDynamicSharedMemorySize, SMEM_BYTES);

    dim3 pg(H_DIM / BJ, T_SEQ / BT);                 // 16 x 8 = 128 blocks
    pre_gemm<<<pg, 128>>>(word, W_i2h1, b_i2h1, b_h2h1);
    rnn_persistent<<<GRID_P, NTHR, SMEM_BYTES>>>(W_h2h1, W_i2h2, b_i2h2,
                                                 W_h2h2, b_h2h2);
    out_gemv<<<OUT_DIM / 8, 256>>>(W_h2o2, b_h2o2, out);
}

// round 3
// speedup vs baseline: 1.5822x; 1.5822x over previous
#include <cuda_runtime.h>
#include <math.h>

#define T_SEQ   512
#define IN_DIM  1024
#define H_DIM   2048
#define OUT_DIM 1024
#define GRID_P  148
#define NTHR    256
#define MAXR    14                          // ceil(2048/148)
#define SMEM_BYTES (2 * MAXR * H_DIM * 4)   // 229376 B dynamic: W_h2h1 + W_h2h2

// ---------------- device scratch (no allocation allowed) --------------------
__device__ float g_pre1[(size_t)T_SEQ * H_DIM];   // x@W_i2h1^T + b_i2h1 + b_h2h1
__device__ float g_h1[2][H_DIM];
__device__ float g_h2[2][H_DIM];
__device__ unsigned g_bar_count;
__device__ unsigned g_bar_gen;

__device__ __forceinline__ float dot4(float4 a, float4 b) {
    return a.x * b.x + a.y * b.y + a.z * b.z + a.w * b.w;
}

// Grid barrier: release-atomic arrive + acquire spin (no membar.gl).
// All GRID_P CTAs co-resident (229KB smem -> 1 CTA/SM, 148 <= SM count).
__device__ __forceinline__ void grid_bar(unsigned target) {
    __syncthreads();
    if (threadIdx.x == 0) {
        unsigned old;
        asm volatile("atom.add.release.gpu.u32 %0, [%1], %2;"
                     : "=r"(old) : "l"(&g_bar_count), "r"(1u) : "memory");
        if (old == GRID_P - 1u) {
            g_bar_count = 0;
            asm volatile("st.release.gpu.u32 [%0], %1;"
                         :: "l"(&g_bar_gen), "r"(target) : "memory");
        } else {
            unsigned g;
            do {
                asm volatile("ld.acquire.gpu.u32 %0, [%1];"
                             : "=r"(g) : "l"(&g_bar_gen) : "memory");
            } while (g != target);
        }
    }
    __syncthreads();
}

// ---------------------------------------------------------------------------
// Kernel 1: pre1[t][j] = x[t] @ W_i2h1[j] + b_i2h1[j] + b_h2h1[j]
// ---------------------------------------------------------------------------
#define BT 64
#define BJ 128
#define BK 32

__global__ __launch_bounds__(128) void pre_gemm(
    const float* __restrict__ X, const float* __restrict__ W,
    const float* __restrict__ b1, const float* __restrict__ b2)
{
    // reset grid-barrier state for the persistent kernel (each replay)
    if (blockIdx.x == 0 && blockIdx.y == 0 && threadIdx.x == 0) {
        g_bar_count = 0; g_bar_gen = 0;
    }

    __shared__ float Xs[BT][BK + 1];
    __shared__ float Ws[BJ][BK + 1];
    const int tid = threadIdx.x;
    const int bt = blockIdx.y * BT;
    const int bj = blockIdx.x * BJ;
    const int tx = tid & 15;
    const int ty = tid >> 4;

    float acc[8][8];
#pragma unroll
    for (int i = 0; i < 8; i++)
#pragma unroll
        for (int j = 0; j < 8; j++) acc[i][j] = 0.f;

    for (int k0 = 0; k0 < IN_DIM; k0 += BK) {
#pragma unroll
        for (int i = tid; i < BT * (BK / 4); i += 128) {
            int t = i / (BK / 4), kq = i % (BK / 4);
            float4 v = *(const float4*)(X + (size_t)(bt + t) * IN_DIM + k0 + kq * 4);
            Xs[t][kq * 4 + 0] = v.x; Xs[t][kq * 4 + 1] = v.y;
            Xs[t][kq * 4 + 2] = v.z; Xs[t][kq * 4 + 3] = v.w;
        }
#pragma unroll
        for (int i = tid; i < BJ * (BK / 4); i += 128) {
            int j = i / (BK / 4), kq = i % (BK / 4);
            float4 v = *(const float4*)(W + (size_t)(bj + j) * IN_DIM + k0 + kq * 4);
            Ws[j][kq * 4 + 0] = v.x; Ws[j][kq * 4 + 1] = v.y;
            Ws[j][kq * 4 + 2] = v.z; Ws[j][kq * 4 + 3] = v.w;
        }
        __syncthreads();
#pragma unroll 8
        for (int kk = 0; kk < BK; kk++) {
            float a[8], b[8];
#pragma unroll
            for (int i = 0; i < 8; i++) a[i] = Xs[ty * 8 + i][kk];
#pragma unroll
            for (int j = 0; j < 8; j++) b[j] = Ws[tx * 8 + j][kk];
#pragma unroll
            for (int i = 0; i < 8; i++)
#pragma unroll
                for (int j = 0; j < 8; j++) acc[i][j] += a[i] * b[j];
        }
        __syncthreads();
    }
#pragma unroll
    for (int i = 0; i < 8; i++) {
        int t = bt + ty * 8 + i;
#pragma unroll
        for (int j = 0; j < 8; j++) {
            int col = bj + tx * 8 + j;
            g_pre1[(size_t)t * H_DIM + col] = acc[i][j] + __ldg(b1 + col) + __ldg(b2 + col);
        }
    }
}

// ---------------------------------------------------------------------------
// Kernel 2: persistent RNN. One grid barrier per step (after phase A).
// Stage-1 reduce: 3 xor-shuffles -> 4 partials/warp -> red[row][32] (2KB).
// Stage-2 reduce: 4 full warps, 8 threads/row, float4 + width-8 shfl_down.
// ---------------------------------------------------------------------------
__global__ __launch_bounds__(NTHR, 1) void rnn_persistent(
    const float* __restrict__ W_h2h1,
    const float* __restrict__ W_i2h2,
    const float* __restrict__ b_i2h2,
    const float* __restrict__ W_h2h2,
    const float* __restrict__ b_h2h2)
{
    extern __shared__ float smem[];
    float* Wsh1 = smem;                    // [MAXR][2048]
    float* Wsh2 = smem + MAXR * H_DIM;     // [MAXR][2048]
    __shared__ __align__(16) float red[16][32];   // 2KB, single buffer
    __shared__ float bsum[16];

    const int tid = threadIdx.x;
    const int bid = blockIdx.x;
    const int r0 = (bid * H_DIM) / GRID_P;
    const int r1 = ((bid + 1) * H_DIM) / GRID_P;
    const int nr = r1 - r0;                // 13 or 14
    const int lane = tid & 31;
    const int wid = tid >> 5;

    // init h2 odd buffer (phase B of t=0 reads g_h2[1]); fused layer-2 bias
    if (tid < nr) {
        g_h2[1][r0 + tid] = 0.f;
        bsum[tid] = __ldg(b_i2h2 + r0 + tid) + __ldg(b_h2h2 + r0 + tid);
    }

    // SMEM weight caches (own rows of W_h2h1, W_h2h2)
    {
        const float4* s1 = (const float4*)(W_h2h1 + (size_t)r0 * H_DIM);
        const float4* s2 = (const float4*)(W_h2h2 + (size_t)r0 * H_DIM);
        float4* d1 = (float4*)Wsh1;
        float4* d2 = (float4*)Wsh2;
        const int n4 = nr * (H_DIM / 4);
        for (int i = tid; i < n4; i += NTHR) { d1[i] = s1[i]; d2[i] = s2[i]; }
    }

    // Register-stationary W_i2h2 slices (cols 4*tid.. and 1024+4*tid..)
    float4 wr0[MAXR], wr1[MAXR];
#pragma unroll
    for (int rr = 0; rr < MAXR; rr++) {
        int r = (rr < nr) ? (r0 + rr) : r0;
        const float4* wp = (const float4*)(W_i2h2 + (size_t)r * H_DIM);
        wr0[rr] = wp[tid];
        wr1[rr] = wp[tid + 256];
    }

    unsigned bt_ = 1;
    grid_bar(bt_);

    const int frow = tid >> 3;             // stage-2 row (0..31 for tid<256)
    const int fs = tid & 7;                // stage-2 float4 index
    const int prow = (frow < nr) ? frow : (nr - 1);   // clamped prefetch row

    float4 a0 = make_float4(0.f, 0.f, 0.f, 0.f), a1 = a0;   // h1(t-1) slice

    for (int t = 0; t < T_SEQ; t++) {
        const int q = t & 1;

        // protect red[] against previous iteration's phase-B stage-2 reads
        __syncthreads();

        // ---- phase A: h1(t) = tanh(pre1[t] + W_h2h1 @ h1(t-1)) ----
        float pre = __ldg(&g_pre1[(size_t)t * H_DIM + r0 + prow]);  // prefetch
#pragma unroll
        for (int rr = 0; rr < MAXR; rr++) {
            const float* w = Wsh1 + rr * H_DIM;
            float4 w0 = *(const float4*)(w + 4 * tid);
            float4 w1 = *(const float4*)(w + 4 * tid + 1024);
            float acc = dot4(w0, a0) + dot4(w1, a1);
            acc += __shfl_xor_sync(0xffffffffu, acc, 16);
            acc += __shfl_xor_sync(0xffffffffu, acc, 8);
            acc += __shfl_xor_sync(0xffffffffu, acc, 4);
            if (lane < 4) red[rr][wid * 4 + lane] = acc;
        }
        __syncthreads();
        if (tid < 128) {                    // 4 full warps
            float4 v = *((const float4*)red[frow] + fs);
            float x = (v.x + v.y) + (v.z + v.w);
            x += __shfl_down_sync(0xffffffffu, x, 4, 8);
            x += __shfl_down_sync(0xffffffffu, x, 2, 8);
            x += __shfl_down_sync(0xffffffffu, x, 1, 8);
            if (fs == 0 && frow < nr)
                g_h1[q][r0 + frow] = tanhf(pre + x);
        }
        grid_bar(++bt_);    // the ONLY grid barrier of the step

        // ---- phase B: h2(t) = tanh(W_i2h2@h1(t) + W_h2h2@h2(t-1) + b) ----
        float4 n0 = __ldcg((const float4*)g_h1[q] + tid);
        float4 n1 = __ldcg((const float4*)g_h1[q] + tid + 256);
        float4 c0 = __ldcg((const float4*)g_h2[1 - q] + tid);
        float4 c1 = __ldcg((const float4*)g_h2[1 - q] + tid + 256);
#pragma unroll
        for (int rr = 0; rr < MAXR; rr++) {
            const float* w = Wsh2 + rr * H_DIM;
            float4 w0 = *(const float4*)(w + 4 * tid);
            float4 w1 = *(const float4*)(w + 4 * tid + 1024);
            float acc = dot4(wr0[rr], n0) + dot4(wr1[rr], n1)
                      + dot4(w0, c0) + dot4(w1, c1);
            acc += __shfl_xor_sync(0xffffffffu, acc, 16);
            acc += __shfl_xor_sync(0xffffffffu, acc, 8);
            acc += __shfl_xor_sync(0xffffffffu, acc, 4);
            if (lane < 4) red[rr][wid * 4 + lane] = acc;
        }
        __syncthreads();
        if (tid < 128) {
            float4 v = *((const float4*)red[frow] + fs);
            float x = (v.x + v.y) + (v.z + v.w);
            x += __shfl_down_sync(0xffffffffu, x, 4, 8);
            x += __shfl_down_sync(0xffffffffu, x, 2, 8);
            x += __shfl_down_sync(0xffffffffu, x, 1, 8);
            if (fs == 0 && frow < nr)
                g_h2[q][r0 + frow] = tanhf(bsum[frow] + x);
        }
        a0 = n0; a1 = n1;   // h1(t) slice becomes next step's h1(t-1)
        // no end-of-step barrier: next step's post-A barrier orders everything
    }
    // final h2 (t=511, q=1) is in g_h2[1]
}

// ---------------------------------------------------------------------------
// Kernel 3: out = h2_final @ W_h2o2^T + b_h2o2
// ---------------------------------------------------------------------------
__global__ __launch_bounds__(256) void out_gemv(
    const float* __restrict__ W, const float* __restrict__ b,
    float* __restrict__ out)
{
    const int lane = threadIdx.x & 31;
    const int warp = threadIdx.x >> 5;
    const int row = blockIdx.x * 8 + warp;
    const float4* wp = (const float4*)(W + (size_t)row * H_DIM);
    const float4* hp = (const float4*)g_h2[1];
    float acc = 0.f;
#pragma unroll
    for (int i = 0; i < 16; i++) {
        float4 w4 = __ldg(wp + i * 32 + lane);
        float4 h4 = __ldcg(hp + i * 32 + lane);
        acc += dot4(w4, h4);
    }
#pragma unroll
    for (int off = 16; off; off >>= 1)
        acc += __shfl_xor_sync(0xffffffffu, acc, off);
    if (lane == 0) out[row] = acc + __ldg(b + row);
}

// ---------------------------------------------------------------------------
extern "C" void kernel_launch(void* const* d_in, const int* in_sizes, int n_in,
                              void* d_out, int out_size)
{
    const float* word   = (const float*)d_in[0];
    const float* W_i2h1 = (const float*)d_in[1];
    const float* b_i2h1 = (const float*)d_in[2];
    const float* W_h2h1 = (const float*)d_in[3];
    const float* b_h2h1 = (const float*)d_in[4];
    // d_in[5], d_in[6]: W_h2o1 / b_h2o1 — dead code in reference
    const float* W_i2h2 = (const float*)d_in[7];
    const float* b_i2h2 = (const float*)d_in[8];
    const float* W_h2h2 = (const float*)d_in[9];
    const float* b_h2h2 = (const float*)d_in[10];
    const float* W_h2o2 = (const float*)d_in[11];
    const float* b_h2o2 = (const float*)d_in[12];
    float* out = (float*)d_out;

    cudaFuncSetAttribute(rnn_persistent,
                         cudaFuncAttributeMaxDynamicSharedMemorySize, SMEM_BYTES);

    dim3 pg(H_DIM / BJ, T_SEQ / BT);
    pre_gemm<<<pg, 128>>>(word, W_i2h1, b_i2h1, b_h2h1);
    rnn_persistent<<<GRID_P, NTHR, SMEM_BYTES>>>(W_h2h1, W_i2h2, b_i2h2,
                                                 W_h2h2, b_h2h2);
    out_gemv<<<OUT_DIM / 8, 256>>>(W_h2o2, b_h2o2, out);
}